// round 14
// baseline (speedup 1.0000x reference)
#include <cuda_runtime.h>
#include <cuda_fp16.h>
#include <cstdint>
#include <mma.h>
#include <math.h>

using namespace nvcuda;

#define HDIM 2880
#define NEXP 16
#define I2   5760
#define IDIM 2880
#define NTOK 1024
#define TOPK 4
#define ALPHA_C 1.702f
#define LIMIT_C 7.0f

#define BM 128
#define BN 64
#define BK 32
#define LDSH 40                  // halves per smem row (32 + 8 pad) = 80B
#define ASTG_B 10240             // A stage bytes: 128 rows * 80B
#define BSTG_B 5120              // B stage bytes: 64 rows * 80B
#define LDS_C 68                 // sC row: 64 + 4 pad floats
#define SMEM_DYN (3 * ASTG_B + 2 * BSTG_B)   // 40960 (sC 34816 fits inside)

// -------- device scratch --------
__device__ int    g_cnt[NEXP];
__device__ int    g_tok[NEXP * NTOK];
__device__ float  g_prob[NEXP * NTOK];
__device__ __half g_xh[(size_t)NTOK * HDIM];
__device__ __half g_acth[(size_t)NEXP * NTOK * IDIM];

// ---------------- helpers ----------------
__device__ __forceinline__ unsigned int smem_u32(const void* p) {
    return (unsigned int)__cvta_generic_to_shared(p);
}
__device__ __forceinline__ void cp16(unsigned int saddr, const void* g) {
    asm volatile("cp.async.cg.shared.global [%0], [%1], 16;\n" :: "r"(saddr), "l"(g));
}
__device__ __forceinline__ void cp_commit() { asm volatile("cp.async.commit_group;\n"); }
template<int N> __device__ __forceinline__ void cp_wait() {
    asm volatile("cp.async.wait_group %0;\n" :: "n"(N));
}

// =========================================================
__global__ void zero_kernel(float4* __restrict__ out) {
    int i = blockIdx.x * blockDim.x + threadIdx.x;
    if (i < NTOK * HDIM / 4) out[i] = make_float4(0.f, 0.f, 0.f, 0.f);
    if (i < NEXP) g_cnt[i] = 0;
}

// hidden fp32 -> fp16 (tiny: 5.9 MB)
__global__ void cvt_hidden(const float4* __restrict__ src) {
    size_t i = (size_t)blockIdx.x * blockDim.x + threadIdx.x;
    float4 v = src[i];
    half2* dst = (half2*)g_xh;
    dst[2 * i]     = __floats2half2_rn(v.x, v.y);
    dst[2 * i + 1] = __floats2half2_rn(v.z, v.w);
}

// =========================================================
__global__ void router_kernel(const float* __restrict__ x,
                              const float* __restrict__ rw,
                              const float* __restrict__ rb) {
    int t = blockIdx.x;
    const float* xr = x + t * HDIM;
    float acc[NEXP];
#pragma unroll
    for (int e = 0; e < NEXP; e++) acc[e] = 0.0f;
    for (int h = threadIdx.x; h < HDIM; h += 128) {
        float xv = xr[h];
#pragma unroll
        for (int e = 0; e < NEXP; e++) acc[e] += xv * rw[e * HDIM + h];
    }
#pragma unroll
    for (int e = 0; e < NEXP; e++) {
#pragma unroll
        for (int o = 16; o > 0; o >>= 1)
            acc[e] += __shfl_down_sync(0xffffffffu, acc[e], o);
    }
    __shared__ float red[4][NEXP];
    int warp = threadIdx.x >> 5, lane = threadIdx.x & 31;
    if (lane == 0) {
#pragma unroll
        for (int e = 0; e < NEXP; e++) red[warp][e] = acc[e];
    }
    __syncthreads();
    if (threadIdx.x == 0) {
        float lg[NEXP];
#pragma unroll
        for (int e = 0; e < NEXP; e++)
            lg[e] = red[0][e] + red[1][e] + red[2][e] + red[3][e] + rb[e];
        int idx[TOPK]; float val[TOPK]; bool used[NEXP];
#pragma unroll
        for (int e = 0; e < NEXP; e++) used[e] = false;
        for (int k = 0; k < TOPK; k++) {
            int bi = -1; float bv = -3.0e38f;
            for (int e = 0; e < NEXP; e++)
                if (!used[e] && lg[e] > bv) { bv = lg[e]; bi = e; }
            used[bi] = true; idx[k] = bi; val[k] = bv;
        }
        float m = val[0], s = 0.0f, p[TOPK];
        for (int k = 0; k < TOPK; k++) { p[k] = expf(val[k] - m); s += p[k]; }
        for (int k = 0; k < TOPK; k++) {
            int e = idx[k];
            int pos = atomicAdd(&g_cnt[e], 1);
            g_tok[e * NTOK + pos]  = t;
            g_prob[e * NTOK + pos] = p[k] / s;
        }
    }
}

// =========================================================
// fp16 grouped GEMM, 128x64 CTA tile, 256 threads (8 warps),
// warp tile 32x32 (accum = 32 regs) -> 3 CTAs/SM forced.
// A (fp16 gmem): 3-stage cp.async ring (R6 schedule).
// B (fp32 weights): LDG.128 -> regs -> cvt -> STS fp16, 2-stage.
// MODE 0: A = gathered g_xh, B = w1 fp32, epilogue glu -> g_acth
// MODE 1: A = g_acth,        B = w2 fp32, epilogue bias+prob -> atomic out
// =========================================================
template<int MODE>
__global__ void __launch_bounds__(256, 3)
moe_gemm(const float* __restrict__ W,
         const float* __restrict__ bias,
         float* __restrict__ out) {
    int e   = blockIdx.z;
    int cnt = g_cnt[e];
    int m0  = blockIdx.x * BM;
    if (m0 >= cnt) return;
    int n0  = blockIdx.y * BN;

    const int KDIM  = 2880;                     // HDIM == IDIM
    const int KT    = KDIM / BK;                // 90
    const int BROWS = (MODE == 0) ? I2 : HDIM;

    extern __shared__ char dsm[];
    half* stgA[3];
    half* stgB[2];
#pragma unroll
    for (int s = 0; s < 3; s++) stgA[s] = (half*)(dsm + s * ASTG_B);
#pragma unroll
    for (int s = 0; s < 2; s++) stgB[s] = (half*)(dsm + 3 * ASTG_B + s * BSTG_B);

    int tid  = threadIdx.x;
    int wid  = tid >> 5, lane = tid & 31;
    int wm   = wid >> 1, wn = wid & 1;          // 4 x 2 warp grid of 32x32 tiles

    // ---- A copy assignment: 2 x 16B chunks per thread (512 chunks/stage) ----
    const half* ap[2];
    unsigned int aoff[2];
#pragma unroll
    for (int i = 0; i < 2; i++) {
        int id  = tid + i * 256;           // 0..511
        int row = id >> 2, q = id & 3;     // 128 rows x 4 chunks(16B)
        aoff[i] = row * 80 + q * 16;
        int rg = m0 + row;
        int rc = (rg < cnt) ? rg : cnt - 1;
        if (MODE == 0) {
            ap[i] = g_xh + (size_t)g_tok[e * NTOK + rc] * HDIM + q * 8;
        } else {
            ap[i] = g_acth + (size_t)(e * NTOK + rc) * IDIM + q * 8;
        }
    }

    // ---- B load assignment: 2 x float4 chunks per thread (512 chunks/stage) ----
    const float* bp[2];
    unsigned int boff[2];
    {
        const float* wbase = W + (size_t)e * BROWS * KDIM;
#pragma unroll
        for (int i = 0; i < 2; i++) {
            int id  = tid + i * 256;       // 0..511
            int row = id >> 3, q = id & 7; // 64 rows x 8 chunks(4 fp32)
            boff[i] = row * 80 + q * 8;    // fp16 smem bytes
            int rb  = n0 + row; if (rb >= BROWS) rb = BROWS - 1;
            bp[i] = wbase + (size_t)rb * KDIM + q * 4;
        }
    }

    auto ldgB = [&](float4* r, int kt) {
        int koff = kt * BK;
#pragma unroll
        for (int i = 0; i < 2; i++)
            r[i] = *reinterpret_cast<const float4*>(bp[i] + koff);
    };
    auto stsB = [&](const float4* r, int b) {
        unsigned int base = smem_u32(stgB[b]);
#pragma unroll
        for (int i = 0; i < 2; i++) {
            half2 h0 = __floats2half2_rn(r[i].x, r[i].y);
            half2 h1 = __floats2half2_rn(r[i].z, r[i].w);
            unsigned int u0 = *(unsigned int*)&h0;
            unsigned int u1 = *(unsigned int*)&h1;
            asm volatile("st.shared.v2.b32 [%0], {%1, %2};\n"
                         :: "r"(base + boff[i]), "r"(u0), "r"(u1));
        }
    };
    auto issueA = [&](int s, int kt) {
        int koff = kt * BK;
        unsigned int a0 = smem_u32(stgA[s]);
#pragma unroll
        for (int i = 0; i < 2; i++) cp16(a0 + aoff[i], ap[i] + koff);
        cp_commit();
    };

    wmma::fragment<wmma::accumulator, 16, 16, 16, float> c[2][2];
#pragma unroll
    for (int i = 0; i < 2; i++)
#pragma unroll
        for (int j = 0; j < 2; j++) wmma::fill_fragment(c[i][j], 0.0f);

    // ---- prologue (R6 schedule) ----
    float4 breg[2];
    issueA(0, 0);
    issueA(1, 1);
    ldgB(breg, 0);
    stsB(breg, 0);
    ldgB(breg, 1);              // held for iter 0's STS

    for (int kt = 0; kt < KT; kt++) {
        int s = kt % 3;
        int b = kt & 1;
        if (kt + 1 < KT) cp_wait<1>(); else cp_wait<0>();
        __syncthreads();

        const half* sa = stgA[s];
        const half* sb = stgB[b];
#pragma unroll
        for (int kk = 0; kk < 2; kk++) {
            wmma::fragment<wmma::matrix_a, 16, 16, 16, half, wmma::row_major> af[2];
#pragma unroll
            for (int i = 0; i < 2; i++)
                wmma::load_matrix_sync(af[i], sa + (wm * 32 + i * 16) * LDSH + kk * 16, LDSH);
#pragma unroll
            for (int j = 0; j < 2; j++) {
                wmma::fragment<wmma::matrix_b, 16, 16, 16, half, wmma::col_major> bf;
                wmma::load_matrix_sync(bf, sb + (wn * 32 + j * 16) * LDSH + kk * 16, LDSH);
#pragma unroll
                for (int i = 0; i < 2; i++)
                    wmma::mma_sync(c[i][j], af[i], bf, c[i][j]);
            }
        }

        if (kt + 1 < KT) stsB(breg, b ^ 1);     // breg holds kt+1
        if (kt + 2 < KT) {
            ldgB(breg, kt + 2);
            issueA((kt + 2) % 3, kt + 2);
        }
    }

    __syncthreads();          // stage smem dead; reuse as sC
    float* sC = (float*)dsm;
#pragma unroll
    for (int i = 0; i < 2; i++)
#pragma unroll
        for (int j = 0; j < 2; j++)
            wmma::store_matrix_sync(&sC[(wm * 32 + i * 16) * LDS_C + wn * 32 + j * 16],
                                    c[i][j], LDS_C, wmma::mem_row_major);
    __syncthreads();

    if (MODE == 0) {
        // vectorized glu epilogue: 8 pairs (16 floats) per thread per step
        const float* b1e = bias + (size_t)e * I2 + n0;
        for (int idx = tid; idx < BM * 4; idx += 256) {
            int row = idx >> 2;          // 0..127
            int g   = idx & 3;           // 4 groups of 8 pairs (64 floats/row)
            int rg  = m0 + row;
            if (rg >= cnt) continue;
            const float4* csrc = (const float4*)(sC + row * LDS_C + 16 * g);
            const float4* bsrc = (const float4*)(b1e + 16 * g);
            __half hout[8];
#pragma unroll
            for (int v = 0; v < 4; v++) {
                float4 cv = csrc[v];
                float4 bv = bsrc[v];
                float gate0 = cv.x + bv.x, up0 = cv.y + bv.y;
                float gate1 = cv.z + bv.z, up1 = cv.w + bv.w;
                gate0 = fminf(gate0, LIMIT_C);
                gate1 = fminf(gate1, LIMIT_C);
                up0 = fminf(fmaxf(up0, -LIMIT_C), LIMIT_C);
                up1 = fminf(fmaxf(up1, -LIMIT_C), LIMIT_C);
                float a0 = (up0 + 1.0f) * (gate0 / (1.0f + __expf(-ALPHA_C * gate0)));
                float a1 = (up1 + 1.0f) * (gate1 / (1.0f + __expf(-ALPHA_C * gate1)));
                hout[2 * v]     = __float2half_rn(a0);
                hout[2 * v + 1] = __float2half_rn(a1);
            }
            *(uint4*)(g_acth + (size_t)(e * NTOK + rg) * IDIM + (n0 >> 1) + 8 * g) =
                *(const uint4*)hout;
        }
    } else {
        // vectorized bias+prob epilogue: 4 cols per thread per step
        const float* b2e = bias + (size_t)e * HDIM;
        for (int idx = tid; idx < BM * 16; idx += 256) {
            int row = idx >> 4;          // 0..127
            int g   = idx & 15;          // 16 groups of 4 cols
            int rg  = m0 + row;
            if (rg >= cnt) continue;
            int nc0 = n0 + 4 * g;
            float prob = g_prob[e * NTOK + rg];
            int   tok  = g_tok[e * NTOK + rg];
            float4 cv = *(const float4*)(sC + row * LDS_C + 4 * g);
            float4 bv = *(const float4*)(b2e + nc0);
            float* orow = out + (size_t)tok * HDIM + nc0;
            atomicAdd(orow + 0, (cv.x + bv.x) * prob);
            atomicAdd(orow + 1, (cv.y + bv.y) * prob);
            atomicAdd(orow + 2, (cv.z + bv.z) * prob);
            atomicAdd(orow + 3, (cv.w + bv.w) * prob);
        }
    }
}

// =========================================================
extern "C" void kernel_launch(void* const* d_in, const int* in_sizes, int n_in,
                              void* d_out, int out_size) {
    const float* hidden = (const float*)d_in[0];
    const float* rw     = (const float*)d_in[1];
    const float* rb     = (const float*)d_in[2];
    const float* w1     = (const float*)d_in[3];
    const float* b1     = (const float*)d_in[4];
    const float* w2     = (const float*)d_in[5];
    const float* b2     = (const float*)d_in[6];
    float* out = (float*)d_out;

    cudaFuncSetAttribute(moe_gemm<0>, cudaFuncAttributeMaxDynamicSharedMemorySize, SMEM_DYN);
    cudaFuncSetAttribute(moe_gemm<1>, cudaFuncAttributeMaxDynamicSharedMemorySize, SMEM_DYN);

    zero_kernel<<<(NTOK * HDIM / 4 + 255) / 256, 256>>>((float4*)out);
    router_kernel<<<NTOK, 128>>>(hidden, rw, rb);
    cvt_hidden<<<2880, 256>>>((const float4*)hidden);   // 1024*2880/4/256

    moe_gemm<0><<<dim3(NTOK / BM, I2 / BN, NEXP), 256, SMEM_DYN>>>(w1, b1, nullptr);
    moe_gemm<1><<<dim3(NTOK / BM, HDIM / BN, NEXP), 256, SMEM_DYN>>>(w2, b2, out);
}

// round 15
// speedup vs baseline: 1.2326x; 1.2326x over previous
#include <cuda_runtime.h>
#include <cuda_fp16.h>
#include <cstdint>
#include <mma.h>
#include <math.h>

using namespace nvcuda;

#define HDIM 2880
#define NEXP 16
#define I2   5760
#define IDIM 2880
#define NTOK 1024
#define TOPK 4
#define ALPHA_C 1.702f
#define LIMIT_C 7.0f

#define BM 128
#define BN 128
#define BK 32
#define LDSH 40                  // halves per smem row (32 + 8 pad) = 80B
#define ASTG_B 10240             // A stage bytes: 128 rows * 80B
#define BSTG_B 10240             // B stage bytes: 128 rows * 80B
#define LDS_C 132
#define SMEM_DYN (BM * LDS_C * 4)   // 67584 (stages use 3*10240 + 2*10240 = 51200)

// -------- device scratch --------
__device__ int    g_cnt[NEXP];
__device__ int    g_tok[NEXP * NTOK];
__device__ float  g_prob[NEXP * NTOK];
__device__ int    g_back[NTOK * TOPK];                 // token -> e*NTOK+pos
__device__ __half g_xh[(size_t)NTOK * HDIM];
__device__ __half g_acth[(size_t)NEXP * NTOK * IDIM];
__device__ float  g_oscr[(size_t)NEXP * NTOK * HDIM];  // ffn2 per-slot output

// ---------------- helpers ----------------
__device__ __forceinline__ unsigned int smem_u32(const void* p) {
    return (unsigned int)__cvta_generic_to_shared(p);
}
__device__ __forceinline__ void cp16(unsigned int saddr, const void* g) {
    asm volatile("cp.async.cg.shared.global [%0], [%1], 16;\n" :: "r"(saddr), "l"(g));
}
__device__ __forceinline__ void cp_commit() { asm volatile("cp.async.commit_group;\n"); }
template<int N> __device__ __forceinline__ void cp_wait() {
    asm volatile("cp.async.wait_group %0;\n" :: "n"(N));
}

// =========================================================
__global__ void init_kernel() {
    int i = blockIdx.x * blockDim.x + threadIdx.x;
    if (i < NEXP) g_cnt[i] = 0;
}

// hidden fp32 -> fp16 (tiny: 5.9 MB)
__global__ void cvt_hidden(const float4* __restrict__ src) {
    size_t i = (size_t)blockIdx.x * blockDim.x + threadIdx.x;
    float4 v = src[i];
    half2* dst = (half2*)g_xh;
    dst[2 * i]     = __floats2half2_rn(v.x, v.y);
    dst[2 * i + 1] = __floats2half2_rn(v.z, v.w);
}

// =========================================================
__global__ void router_kernel(const float* __restrict__ x,
                              const float* __restrict__ rw,
                              const float* __restrict__ rb) {
    int t = blockIdx.x;
    const float* xr = x + t * HDIM;
    float acc[NEXP];
#pragma unroll
    for (int e = 0; e < NEXP; e++) acc[e] = 0.0f;
    for (int h = threadIdx.x; h < HDIM; h += 128) {
        float xv = xr[h];
#pragma unroll
        for (int e = 0; e < NEXP; e++) acc[e] += xv * rw[e * HDIM + h];
    }
#pragma unroll
    for (int e = 0; e < NEXP; e++) {
#pragma unroll
        for (int o = 16; o > 0; o >>= 1)
            acc[e] += __shfl_down_sync(0xffffffffu, acc[e], o);
    }
    __shared__ float red[4][NEXP];
    int warp = threadIdx.x >> 5, lane = threadIdx.x & 31;
    if (lane == 0) {
#pragma unroll
        for (int e = 0; e < NEXP; e++) red[warp][e] = acc[e];
    }
    __syncthreads();
    if (threadIdx.x == 0) {
        float lg[NEXP];
#pragma unroll
        for (int e = 0; e < NEXP; e++)
            lg[e] = red[0][e] + red[1][e] + red[2][e] + red[3][e] + rb[e];
        int idx[TOPK]; float val[TOPK]; bool used[NEXP];
#pragma unroll
        for (int e = 0; e < NEXP; e++) used[e] = false;
        for (int k = 0; k < TOPK; k++) {
            int bi = -1; float bv = -3.0e38f;
            for (int e = 0; e < NEXP; e++)
                if (!used[e] && lg[e] > bv) { bv = lg[e]; bi = e; }
            used[bi] = true; idx[k] = bi; val[k] = bv;
        }
        float m = val[0], s = 0.0f, p[TOPK];
        for (int k = 0; k < TOPK; k++) { p[k] = expf(val[k] - m); s += p[k]; }
        for (int k = 0; k < TOPK; k++) {
            int e = idx[k];
            int pos = atomicAdd(&g_cnt[e], 1);
            g_tok[e * NTOK + pos]  = t;
            g_prob[e * NTOK + pos] = p[k] / s;
            g_back[t * TOPK + k]   = e * NTOK + pos;
        }
    }
}

// =========================================================
// combine: out[t] = sum_k g_oscr[g_back[t][k]]   (float4 lanes)
// =========================================================
__global__ void combine_kernel(float4* __restrict__ out) {
    int i = blockIdx.x * blockDim.x + threadIdx.x;   // over NTOK * HDIM/4
    if (i >= NTOK * (HDIM / 4)) return;
    int t = i / (HDIM / 4);
    int c = i % (HDIM / 4);
    const int* bk = g_back + t * TOPK;
    float4 s = make_float4(0.f, 0.f, 0.f, 0.f);
#pragma unroll
    for (int k = 0; k < TOPK; k++) {
        const float4* src = (const float4*)(g_oscr + (size_t)bk[k] * HDIM) + c;
        float4 v = *src;
        s.x += v.x; s.y += v.y; s.z += v.z; s.w += v.w;
    }
    out[i] = s;
}

// =========================================================
// fp16 grouped GEMM, 128x128 tile, BK=32  (exact R6/R13 mainloop).
// A (fp16 gmem): 3-stage cp.async ring.
// B (fp32 weights): LDG.128 -> regs -> cvt -> STS fp16, 2-stage.
// MODE 0: A = gathered g_xh, B = w1 fp32, epilogue glu -> g_acth
// MODE 1: A = g_acth,        B = w2 fp32, epilogue bias+prob -> g_oscr (plain stores)
// =========================================================
template<int MODE>
__global__ void __launch_bounds__(256)
moe_gemm(const float* __restrict__ W,
         const float* __restrict__ bias) {
    int e   = blockIdx.z;
    int cnt = g_cnt[e];
    int m0  = blockIdx.x * BM;
    if (m0 >= cnt) return;
    int n0  = blockIdx.y * BN;

    const int KDIM  = 2880;                     // HDIM == IDIM
    const int KT    = KDIM / BK;                // 90
    const int BROWS = (MODE == 0) ? I2 : HDIM;

    extern __shared__ char dsm[];
    half* stgA[3];
    half* stgB[2];
#pragma unroll
    for (int s = 0; s < 3; s++) stgA[s] = (half*)(dsm + s * ASTG_B);
#pragma unroll
    for (int s = 0; s < 2; s++) stgB[s] = (half*)(dsm + 3 * ASTG_B + s * BSTG_B);

    int tid  = threadIdx.x;
    int wid  = tid >> 5, lane = tid & 31;
    int wm   = wid >> 1, wn = wid & 1;

    // ---- A copy assignment: 2 x 16B chunks per thread ----
    const half* ap[2];
    unsigned int aoff[2];
#pragma unroll
    for (int i = 0; i < 2; i++) {
        int id  = tid + i * 256;           // 0..511
        int row = id >> 2, q = id & 3;     // 128 rows x 4 chunks
        aoff[i] = row * 80 + q * 16;
        int rg = m0 + row;
        int rc = (rg < cnt) ? rg : cnt - 1;
        if (MODE == 0) {
            ap[i] = g_xh + (size_t)g_tok[e * NTOK + rc] * HDIM + q * 8;
        } else {
            ap[i] = g_acth + (size_t)(e * NTOK + rc) * IDIM + q * 8;
        }
    }

    // ---- B load assignment: 4 x float4 chunks per thread ----
    const float* bp[4];
    unsigned int boff[4];
    {
        const float* wbase = W + (size_t)e * BROWS * KDIM;
#pragma unroll
        for (int i = 0; i < 4; i++) {
            int id  = tid + i * 256;       // 0..1023
            int row = id >> 3, q = id & 7; // 128 rows x 8 chunks(4 fp32)
            boff[i] = row * 80 + q * 8;    // fp16 smem bytes
            int rb  = n0 + row; if (rb >= BROWS) rb = BROWS - 1;
            bp[i] = wbase + (size_t)rb * KDIM + q * 4;
        }
    }

    auto ldgB = [&](float4* r, int kt) {
        int koff = kt * BK;
#pragma unroll
        for (int i = 0; i < 4; i++)
            r[i] = *reinterpret_cast<const float4*>(bp[i] + koff);
    };
    auto stsB = [&](const float4* r, int b) {
        unsigned int base = smem_u32(stgB[b]);
#pragma unroll
        for (int i = 0; i < 4; i++) {
            half2 h0 = __floats2half2_rn(r[i].x, r[i].y);
            half2 h1 = __floats2half2_rn(r[i].z, r[i].w);
            unsigned int u0 = *(unsigned int*)&h0;
            unsigned int u1 = *(unsigned int*)&h1;
            asm volatile("st.shared.v2.b32 [%0], {%1, %2};\n"
                         :: "r"(base + boff[i]), "r"(u0), "r"(u1));
        }
    };
    auto issueA = [&](int s, int kt) {
        int koff = kt * BK;
        unsigned int a0 = smem_u32(stgA[s]);
#pragma unroll
        for (int i = 0; i < 2; i++) cp16(a0 + aoff[i], ap[i] + koff);
        cp_commit();
    };

    wmma::fragment<wmma::accumulator, 16, 16, 16, float> c[2][4];
#pragma unroll
    for (int i = 0; i < 2; i++)
#pragma unroll
        for (int j = 0; j < 4; j++) wmma::fill_fragment(c[i][j], 0.0f);

    // ---- prologue ----
    float4 breg[4];
    issueA(0, 0);
    issueA(1, 1);
    ldgB(breg, 0);
    stsB(breg, 0);
    ldgB(breg, 1);              // held for iter 0's STS

    for (int kt = 0; kt < KT; kt++) {
        int s = kt % 3;
        int b = kt & 1;
        if (kt + 1 < KT) cp_wait<1>(); else cp_wait<0>();
        __syncthreads();

        const half* sa = stgA[s];
        const half* sb = stgB[b];
#pragma unroll
        for (int kk = 0; kk < 2; kk++) {
            wmma::fragment<wmma::matrix_a, 16, 16, 16, half, wmma::row_major> af[2];
#pragma unroll
            for (int i = 0; i < 2; i++)
                wmma::load_matrix_sync(af[i], sa + (wm * 32 + i * 16) * LDSH + kk * 16, LDSH);
#pragma unroll
            for (int j = 0; j < 4; j++) {
                wmma::fragment<wmma::matrix_b, 16, 16, 16, half, wmma::col_major> bf;
                wmma::load_matrix_sync(bf, sb + (wn * 64 + j * 16) * LDSH + kk * 16, LDSH);
#pragma unroll
                for (int i = 0; i < 2; i++)
                    wmma::mma_sync(c[i][j], af[i], bf, c[i][j]);
            }
        }

        if (kt + 1 < KT) stsB(breg, b ^ 1);     // breg holds kt+1
        if (kt + 2 < KT) {
            ldgB(breg, kt + 2);
            issueA((kt + 2) % 3, kt + 2);
        }
    }

    __syncthreads();          // stage smem dead; reuse as sC
    float* sC = (float*)dsm;
#pragma unroll
    for (int i = 0; i < 2; i++)
#pragma unroll
        for (int j = 0; j < 4; j++)
            wmma::store_matrix_sync(&sC[(wm * 32 + i * 16) * LDS_C + wn * 64 + j * 16],
                                    c[i][j], LDS_C, wmma::mem_row_major);
    __syncthreads();

    if (MODE == 0) {
        // vectorized glu epilogue: 8 pairs (16 floats) per thread per step
        const float* b1e = bias + (size_t)e * I2 + n0;
        for (int idx = tid; idx < BM * 8; idx += 256) {
            int row = idx >> 3;          // 0..127
            int g   = idx & 7;           // 8 groups of 8 pairs
            int rg  = m0 + row;
            if (rg >= cnt) continue;
            const float4* csrc = (const float4*)(sC + row * LDS_C + 16 * g);
            const float4* bsrc = (const float4*)(b1e + 16 * g);
            __half hout[8];
#pragma unroll
            for (int v = 0; v < 4; v++) {
                float4 cv = csrc[v];
                float4 bv = bsrc[v];
                float gate0 = cv.x + bv.x, up0 = cv.y + bv.y;
                float gate1 = cv.z + bv.z, up1 = cv.w + bv.w;
                gate0 = fminf(gate0, LIMIT_C);
                gate1 = fminf(gate1, LIMIT_C);
                up0 = fminf(fmaxf(up0, -LIMIT_C), LIMIT_C);
                up1 = fminf(fmaxf(up1, -LIMIT_C), LIMIT_C);
                float a0 = (up0 + 1.0f) * (gate0 / (1.0f + __expf(-ALPHA_C * gate0)));
                float a1 = (up1 + 1.0f) * (gate1 / (1.0f + __expf(-ALPHA_C * gate1)));
                hout[2 * v]     = __float2half_rn(a0);
                hout[2 * v + 1] = __float2half_rn(a1);
            }
            *(uint4*)(g_acth + (size_t)(e * NTOK + rg) * IDIM + (n0 >> 1) + 8 * g) =
                *(const uint4*)hout;
        }
    } else {
        // bias+prob epilogue: plain float4 stores into g_oscr (no atomics)
        const float* b2e = bias + (size_t)e * HDIM;
        for (int idx = tid; idx < BM * 32; idx += 256) {
            int row = idx >> 5;          // 0..127
            int g   = idx & 31;          // 32 groups of 4 cols
            int rg  = m0 + row;
            if (rg >= cnt) continue;
            int nc0 = n0 + 4 * g;
            if (nc0 >= HDIM) continue;
            float prob = g_prob[e * NTOK + rg];
            float4 cv = *(const float4*)(sC + row * LDS_C + 4 * g);
            float4 bv = *(const float4*)(b2e + nc0);
            float4 o;
            o.x = (cv.x + bv.x) * prob;
            o.y = (cv.y + bv.y) * prob;
            o.z = (cv.z + bv.z) * prob;
            o.w = (cv.w + bv.w) * prob;
            *(float4*)(g_oscr + (size_t)(e * NTOK + rg) * HDIM + nc0) = o;
        }
    }
}

// =========================================================
extern "C" void kernel_launch(void* const* d_in, const int* in_sizes, int n_in,
                              void* d_out, int out_size) {
    const float* hidden = (const float*)d_in[0];
    const float* rw     = (const float*)d_in[1];
    const float* rb     = (const float*)d_in[2];
    const float* w1     = (const float*)d_in[3];
    const float* b1     = (const float*)d_in[4];
    const float* w2     = (const float*)d_in[5];
    const float* b2     = (const float*)d_in[6];
    float* out = (float*)d_out;

    cudaFuncSetAttribute(moe_gemm<0>, cudaFuncAttributeMaxDynamicSharedMemorySize, SMEM_DYN);
    cudaFuncSetAttribute(moe_gemm<1>, cudaFuncAttributeMaxDynamicSharedMemorySize, SMEM_DYN);

    init_kernel<<<1, 32>>>();
    router_kernel<<<NTOK, 128>>>(hidden, rw, rb);
    cvt_hidden<<<2880, 256>>>((const float4*)hidden);   // 1024*2880/4/256

    moe_gemm<0><<<dim3(NTOK / BM, I2 / BN, NEXP), 256, SMEM_DYN>>>(w1, b1);
    moe_gemm<1><<<dim3(NTOK / BM, (HDIM + BN - 1) / BN, NEXP), 256, SMEM_DYN>>>(w2, b2);
    combine_kernel<<<(NTOK * (HDIM / 4) + 255) / 256, 256>>>((float4*)out);
}